// round 13
// baseline (speedup 1.0000x reference)
#include <cuda_runtime.h>
#include <cuda_bf16.h>

// Problem dims
#define Bn   128
#define En   1024
#define Kn   64
#define HDn  256
#define ROWSn (7*HDn)   // 1792

// Decomposition: 8 batch-groups x 16 dim-groups = 128 persistent CTAs
#define NB_G 8
#define ND_G 16
#define NCTA (NB_G*ND_G)
#define BT   16          // batches per CTA
#define DTI  16          // hidden dims per CTA
#define NTHREADS 256

// smem strides (floats). Data is k-half packed: f2 = (x[k], x[k+128]), k in [0,128)
#define W2ST 258         // V_w / Lw row stride (floats) -> conflict-free w LDS.64
#define H2ST 260         // ht row stride (floats), 16B-aligned rows for float4 refill
#define REDB 114         // reduction b-stride (f2 cells)
#define REDSL (16*REDB)  // 1824 f2 per k-slice

// smem layout (float offsets)
#define W2_OFF  0                         // 112*258 = 28896
#define H2_OFF  (112*W2ST)                // 28896,  16*260 = 4160
#define LW_OFF  (H2_OFF + BT*H2ST)        // 33056,  4*258 = 1032
#define SC_OFF  (LW_OFF + 4*W2ST)         // 34088,  4
#define MS_OFF  (SC_OFF + 4)              // 34092,  16 (+pad)
#define OUT_OFF (MS_OFF + 20)             // 34112 (16B aligned), 1024
#define RED_OFF (OUT_OFF + 1024)          // 35136,  4*1824*2 = 14592
#define SMEM_FLOATS (RED_OFF + 4*REDSL*2) // 49728
#define SMEM_BYTES  (SMEM_FLOATS*4)       // 198912

// scratch (static __device__ arrays: no allocation allowed)
__device__ int      g_ev[Bn*En];
__device__ float    g_G[Kn*ROWSn];
// ht exchange, k-half packed: float idx = b*256 + kk*2 + lane (kk in [0,128))
__device__ __align__(16) float g_ht2[2][Bn*HDn];
__device__ unsigned g_barc[NB_G][32];
__device__ unsigned g_barg[NB_G][32];
__device__ int      g_mask_mode;   // 0=uint8, 1=int32, 2=float32

typedef unsigned long long ull;

__device__ __forceinline__ float sigf(float x) {
    return __fdividef(1.0f, 1.0f + __expf(-x));
}
__device__ __forceinline__ float4 ldcg4(const float* p) {
    float4 v;
    asm volatile("ld.global.cg.v4.f32 {%0,%1,%2,%3},[%4];"
                 : "=f"(v.x),"=f"(v.y),"=f"(v.z),"=f"(v.w) : "l"(p));
    return v;
}
__device__ __forceinline__ void stcg1(float* p, float v) {
    asm volatile("st.global.cg.f32 [%0],%1;" :: "l"(p),"f"(v) : "memory");
}
// packed dual-fp32 FMA (Blackwell FFMA2) — only reachable via PTX
__device__ __forceinline__ void fma2(ull &acc, ull a, ull b) {
    asm("fma.rn.f32x2 %0,%1,%2,%0;" : "+l"(acc) : "l"(a), "l"(b));
}

// ---------------------------------------------------------------------------
// init: reset barriers + sniff mask dtype (first 256 elems of row0 are all true)
__global__ void k_init(const void* mask) {
    if (threadIdx.x < NB_G) {
        g_barc[threadIdx.x][0] = 0u;
        g_barg[threadIdx.x][0] = 0u;
    }
    if (threadIdx.x == 0) {
        const float* mf = (const float*)mask;
        const int*   mi = (const int*)mask;
        bool okf = true, oki = true, anyf = false, anyi = false;
        for (int j = 0; j < 256; ++j) {
            float fv = mf[j];
            if (!(fv == 0.0f || fv == 1.0f)) okf = false;
            else if (fv == 1.0f) anyf = true;
            int iv = mi[j];
            if (!(iv == 0 || iv == 1)) oki = false;
            else if (iv == 1) anyi = true;
        }
        if      (okf && anyf) g_mask_mode = 2;
        else if (oki && anyi) g_mask_mode = 1;
        else                  g_mask_mode = 0;
    }
}

// one-hot -> index
__global__ void k_ev(const float* __restrict__ seq) {
    int idx = blockIdx.x * blockDim.x + threadIdx.x;   // b*En+e
    if (idx >= Bn*En) return;
    const float4* p = (const float4*)&seq[(size_t)idx * Kn];
    int kv = 0;
    #pragma unroll
    for (int j = 0; j < Kn/4; ++j) {
        float4 v = __ldg(&p[j]);
        if (v.x > 0.5f) kv = j*4;
        else if (v.y > 0.5f) kv = j*4+1;
        else if (v.z > 0.5f) kv = j*4+2;
        else if (v.w > 0.5f) kv = j*4+3;
    }
    g_ev[idx] = kv;
}

// bias table: G[k][r] = U_w[r][k] + U_b[r] + V_b[r]
__global__ void k_G(const float* __restrict__ U_w,
                    const float* __restrict__ U_b,
                    const float* __restrict__ V_b) {
    int idx = blockIdx.x * blockDim.x + threadIdx.x;
    if (idx >= Kn*ROWSn) return;
    int kv = idx / ROWSn;
    int r  = idx - kv * ROWSn;
    g_G[idx] = U_w[r*Kn + kv] + U_b[r] + V_b[r];
}

// ---------------------------------------------------------------------------
__device__ __forceinline__ void bg_barrier(int bg, unsigned want) {
    __syncthreads();
    if (threadIdx.x == 0) {
        __threadfence();
        unsigned t = atomicAdd(&g_barc[bg][0], 1u);
        if (t == ND_G - 1) {
            atomicExch(&g_barc[bg][0], 0u);
            __threadfence();
            atomicAdd(&g_barg[bg][0], 1u);
        } else {
            unsigned v;
            const unsigned* gp = &g_barg[bg][0];
            do {
                __nanosleep(32);
                asm volatile("ld.global.cg.u32 %0,[%1];" : "=r"(v) : "l"(gp));
            } while (v < want);
            __threadfence();
        }
    }
    __syncthreads();
}

// ---------------------------------------------------------------------------
__global__ void __launch_bounds__(NTHREADS, 1)
ctlstm_main(const void*  __restrict__ mask_raw,
            const float* __restrict__ times,
            const float* __restrict__ V_w,
            const float* __restrict__ Lw,
            const float* __restrict__ scale,
            float*       __restrict__ out)
{
    extern __shared__ float sm[];
    float* w2    = sm + W2_OFF;
    float* h2    = sm + H2_OFF;
    float* lw2   = sm + LW_OFF;
    float* sc_s  = sm + SC_OFF;
    float* m_s   = sm + MS_OFF;
    float* out_s = sm + OUT_OFF;
    float* red   = sm + RED_OFF;

    const int tid = threadIdx.x;
    const int cta = blockIdx.x;
    const int bg  = cta & (NB_G - 1);
    const int dg  = cta >> 3;
    const int b0  = bg * BT;
    const int d0  = dg * DTI;

    // pointwise / per-cell mapping
    const int pb  = tid >> 4;             // local batch
    const int pd  = tid & 15;             // local dim
    const int bgl = b0 + pb;
    const int dgl = d0 + pd;

    // GEMM mapping: 4 k-slices x 2 warps; 64 lanes/slice = 16 dims x 4 batch-quads
    const int warp = tid >> 5, lane = tid & 31;
    const int sl   = warp >> 1;            // k-slice 0..3
    const int L    = ((warp & 1) << 5) | lane;
    const int gd   = L & 15;               // dim within CTA
    const int bq   = L >> 4;               // batch quad 0..3 (batches 4bq..4bq+3)
    const int kk0  = sl * 32;

    // lambda mapping
    const int lb    = tid >> 4;            // batch
    const int kslot = tid & 15;

    const int mask_mode = g_mask_mode;

    // ---- prologue: pack V_w slice (k-halves) into smem ---------------------
    for (int i = tid; i < 112*128; i += NTHREADS) {
        int row = i >> 7, kk = i & 127;
        int g = row >> 4, dl = row & 15;
        const float* src = &V_w[(size_t)(g*HDn + d0 + dl)*HDn + kk];
        float2 v; v.x = __ldg(src); v.y = __ldg(src + 128);
        *(float2*)&w2[row*W2ST + kk*2] = v;
    }
    for (int i = tid; i < 4*128; i += NTHREADS) {
        int r = i >> 7, kk = i & 127;
        const float* src = &Lw[(size_t)(dg*4 + r)*HDn + kk];
        float2 v; v.x = __ldg(src); v.y = __ldg(src + 128);
        *(float2*)&lw2[r*W2ST + kk*2] = v;
    }
    if (tid < 4) sc_s[tid] = scale[dg*4 + tid];
    for (int i = tid; i < BT*H2ST; i += NTHREADS) h2[i] = 0.0f;
    __syncthreads();

    float ct = 0.0f, cb = 0.0f, htr = 0.0f;

    const size_t BEH  = (size_t)Bn * En * HDn;
    const size_t OFF1 = (size_t)Bn * En * Kn;
    const int    ln   = dg >> 3;                 // k-half lane for ht store
    const int    kkd  = (dg & 7)*16 + pd;        // packed-k slot for ht store

    const float* hb = &h2[(bq*4)*H2ST + kk0*2];
    const float* wb = &w2[gd*W2ST + kk0*2];

    for (int e = 0; e < En; ++e) {
        // -------- prefetch per-step scalars (hidden under GEMM) -------------
        int kv = g_ev[bgl*En + e];
        float bias[7];
        #pragma unroll
        for (int g = 0; g < 7; ++g)
            bias[g] = __ldg(&g_G[(size_t)kv*ROWSn + g*HDn + dgl]);
        float mval;
        {
            int mi = bgl*En + e;
            if (mask_mode == 0)      mval = ((const unsigned char*)mask_raw)[mi] ? 1.0f : 0.0f;
            else if (mask_mode == 1) mval = ((const int*)mask_raw)[mi] ? 1.0f : 0.0f;
            else                     mval = (((const float*)mask_raw)[mi] != 0.0f) ? 1.0f : 0.0f;
        }
        float dt = times[bgl*(En+1) + e + 1] - times[bgl*(En+1) + e];

        // -------- register-blocked GEMM: 4 batches x 7 gates per thread -----
        ull acc[4][7];
        #pragma unroll
        for (int j = 0; j < 4; ++j)
            #pragma unroll
            for (int g = 0; g < 7; ++g) acc[j][g] = 0ull;

        #pragma unroll 4
        for (int k = 0; k < 32; ++k) {
            ull hv[4];
            #pragma unroll
            for (int j = 0; j < 4; ++j)
                hv[j] = *(const ull*)&hb[j*H2ST + k*2];
            #pragma unroll
            for (int g = 0; g < 7; ++g) {
                ull wv = *(const ull*)&wb[g*(16*W2ST) + k*2];
                #pragma unroll
                for (int j = 0; j < 4; ++j) fma2(acc[j][g], hv[j], wv);
            }
        }
        // store k-slice partials
        #pragma unroll
        for (int j = 0; j < 4; ++j)
            #pragma unroll
            for (int g = 0; g < 7; ++g)
                *(ull*)&red[(sl*REDSL + (bq*4+j)*REDB + g*16 + gd)*2] = acc[j][g];
        __syncthreads();

        // -------- reduce + pointwise recurrence ------------------------------
        float nn[7];
        #pragma unroll
        for (int g = 0; g < 7; ++g) {
            float v = bias[g];
            #pragma unroll
            for (int ss = 0; ss < 4; ++ss) {
                float2 p = *(const float2*)&red[(ss*REDSL + pb*REDB + g*16 + pd)*2];
                v += p.x + p.y;
            }
            nn[g] = v;
        }
        float ig = sigf(nn[0]);
        float fg = sigf(nn[1]);
        float ib = sigf(nn[2]);
        float fb = sigf(nn[3]);
        float z  = 2.0f * sigf(nn[4]);
        float og = sigf(nn[5]);
        float x6 = nn[6];
        float delta = (x6 > 20.0f) ? x6 : log1pf(__expf(x6));   // softplus
        float clow = fg*ct + ig*z;
        float cbn  = fb*cb + ib*z;
        float ctn  = cbn + (clow - cbn) * __expf(-dt*delta);
        float htn  = og * (2.0f*sigf(2.0f*ctn) - 1.0f);
        if (mval != 0.0f) { ct = ctn; cb = cbn; htr = htn; }

        // stage outputs, publish ht
        int cell = pb*16 + pd;
        out_s[0*256 + cell] = mval * clow;
        out_s[1*256 + cell] = mval * cbn;
        out_s[2*256 + cell] = mval * delta;
        out_s[3*256 + cell] = mval * og;
        if (pd == 0) m_s[pb] = mval;
        float* htbuf = g_ht2[e & 1];
        stcg1(&htbuf[bgl*256 + kkd*2 + ln], htr);
        __syncthreads();

        // -------- output stores: 64B-aligned float4 segments ----------------
        {
            int a  = tid >> 6;
            int rr = tid & 63;
            int bb = rr >> 2, d4 = rr & 3;
            float4 v = *(float4*)&out_s[a*256 + bb*16 + d4*4];
            float* dst = out + OFF1 + (size_t)a*BEH
                       + ((size_t)(b0 + bb)*En + e)*HDn + d0 + d4*4;
            *(float4*)dst = v;
        }

        bg_barrier(bg, (unsigned)(e + 1));

        // -------- refill packed ht for my 16 batches -------------------------
        for (int i = tid; i < BT*64; i += NTHREADS) {
            int bb = i >> 6, c = i & 63;
            float4 v = ldcg4(&htbuf[(b0 + bb)*256 + c*4]);
            *(float4*)&h2[bb*H2ST + c*4] = v;
        }
        __syncthreads();

        // -------- lambda: all 8 warps, k-split + shuffle reduce ---------------
        {
            ull la[4] = {0ull, 0ull, 0ull, 0ull};
            const float* hr = &h2[lb*H2ST];
            #pragma unroll
            for (int i = 0; i < 8; ++i) {
                int kk = kslot + i*16;
                ull hv = *(const ull*)&hr[kk*2];
                #pragma unroll
                for (int kl = 0; kl < 4; ++kl) {
                    ull lv = *(const ull*)&lw2[kl*W2ST + kk*2];
                    fma2(la[kl], hv, lv);
                }
            }
            float lam[4];
            #pragma unroll
            for (int kl = 0; kl < 4; ++kl) {
                float2 p = *(float2*)&la[kl];
                #pragma unroll
                for (int off = 8; off > 0; off >>= 1) {
                    p.x += __shfl_xor_sync(0xFFFFFFFFu, p.x, off);
                    p.y += __shfl_xor_sync(0xFFFFFFFFu, p.y, off);
                }
                lam[kl] = p.x + p.y;
            }
            if (kslot == 0) {
                float mv = m_s[lb];
                float4 o4;
                float* o = &o4.x;
                #pragma unroll
                for (int kl = 0; kl < 4; ++kl) {
                    float s  = sc_s[kl];
                    float xx = __fdividef(lam[kl], s);
                    float sp = (xx > 20.0f) ? xx : log1pf(__expf(xx));
                    o[kl] = mv * (s * sp);
                }
                *(float4*)&out[((size_t)(b0 + lb)*En + e)*Kn + dg*4] = o4;
            }
        }
        __syncthreads();   // protect h2 / m_s / out_s for next step
    }
}

// ---------------------------------------------------------------------------
extern "C" void kernel_launch(void* const* d_in, const int* in_sizes, int n_in,
                              void* d_out, int out_size) {
    const float* seq   = (const float*)d_in[0];
    const void*  mask  = d_in[1];
    const float* times = (const float*)d_in[2];
    const float* U_w   = (const float*)d_in[3];
    const float* U_b   = (const float*)d_in[4];
    const float* V_w   = (const float*)d_in[5];
    const float* V_b   = (const float*)d_in[6];
    const float* Lw    = (const float*)d_in[7];
    const float* scale = (const float*)d_in[8];
    float* out = (float*)d_out;

    k_init<<<1, 32>>>(mask);
    k_ev<<<(Bn*En + 127)/128, 128>>>(seq);
    k_G<<<(Kn*ROWSn + 255)/256, 256>>>(U_w, U_b, V_b);

    cudaFuncSetAttribute(ctlstm_main,
                         cudaFuncAttributeMaxDynamicSharedMemorySize, SMEM_BYTES);
    ctlstm_main<<<NCTA, NTHREADS, SMEM_BYTES>>>(mask, times, V_w, Lw, scale, out);
}

// round 15
// speedup vs baseline: 1.6628x; 1.6628x over previous
#include <cuda_runtime.h>
#include <cstdint>

#define Bn 128
#define En 1024
#define Kn 64
#define HDn 256
#define ROWSn 1792
#define NB_G 8
#define ND_G 16
#define NCTA 128
#define NT 256

// smem float offsets
#define HT_ST 260
#define D_ST  18
#define HT_OFF 0                        // 16*260 = 4160
#define D_OFF  (16*HT_ST)               // 4160, 128*18 = 2304
#define OUT_OFF (D_OFF + 128*D_ST)      // 6464, 1024
#define HTO_OFF (OUT_OFF + 1024)        // 7488, 256
#define LAM_OFF (HTO_OFF + 256)         // 7744, 64
#define M_OFF   (LAM_OFF + 64)          // 7808, 32
#define SM_FLOATS (M_OFF + 32)          // 7840 floats = 31360 B (static smem)

__device__ int      g_ev[Bn*En];
__device__ float    g_G[Kn*ROWSn];
__device__ __align__(16) float g_ht[2][Bn*HDn];
__device__ unsigned g_barc[NB_G][32];
__device__ unsigned g_barg[NB_G][32];
__device__ int      g_mask_mode;

__device__ __forceinline__ float sigf(float x){
    return __fdividef(1.0f, 1.0f + __expf(-x));
}
__device__ __forceinline__ float tanhap(float x){
    float y; asm("tanh.approx.f32 %0,%1;" : "=f"(y) : "f"(x)); return y;
}
__device__ __forceinline__ uint32_t tf32r(float f){
    uint32_t u; asm("cvt.rna.tf32.f32 %0,%1;" : "=r"(u) : "f"(f)); return u;
}
__device__ __forceinline__ void stcg4(float* p, float4 v){
    asm volatile("st.global.cg.v4.f32 [%0],{%1,%2,%3,%4};"
                 :: "l"(p),"f"(v.x),"f"(v.y),"f"(v.z),"f"(v.w) : "memory");
}
__device__ __forceinline__ void mma8(float* d, const uint32_t* a,
                                     uint32_t b0, uint32_t b1){
    asm volatile("mma.sync.aligned.m16n8k8.row.col.f32.tf32.tf32.f32 "
        "{%0,%1,%2,%3},{%4,%5,%6,%7},{%8,%9},{%0,%1,%2,%3};"
        : "+f"(d[0]),"+f"(d[1]),"+f"(d[2]),"+f"(d[3])
        : "r"(a[0]),"r"(a[1]),"r"(a[2]),"r"(a[3]),"r"(b0),"r"(b1));
}
__device__ __forceinline__ uint32_t smem_u32(const void* p){
    uint32_t a;
    asm("{ .reg .u64 t; cvta.to.shared.u64 t,%1; cvt.u32.u64 %0,t; }":"=r"(a):"l"(p));
    return a;
}
__device__ __forceinline__ void cpa16(uint32_t dst, const float* src){
    asm volatile("cp.async.cg.shared.global [%0],[%1],16;" :: "r"(dst),"l"(src));
}

__global__ void k_init(const void* mask){
    if (threadIdx.x < NB_G){
        g_barc[threadIdx.x][0] = 0u;
        g_barg[threadIdx.x][0] = 0u;
    }
    if (threadIdx.x == 0){
        const float* mf = (const float*)mask;
        const int*   mi = (const int*)mask;
        bool okf=true, oki=true, anyf=false, anyi=false;
        for (int j=0;j<256;++j){
            float fv=mf[j];
            if(!(fv==0.0f||fv==1.0f)) okf=false; else if(fv==1.0f) anyf=true;
            int iv=mi[j];
            if(!(iv==0||iv==1)) oki=false; else if(iv==1) anyi=true;
        }
        g_mask_mode = (okf&&anyf)?2:((oki&&anyi)?1:0);
    }
}

__global__ void k_ev(const float* __restrict__ seq){
    int idx = blockIdx.x*blockDim.x + threadIdx.x;
    if (idx >= Bn*En) return;
    const float4* p = (const float4*)&seq[(size_t)idx*Kn];
    int kv = 0;
    #pragma unroll
    for (int j=0;j<Kn/4;++j){
        float4 v = __ldg(&p[j]);
        if(v.x>0.5f)kv=j*4; else if(v.y>0.5f)kv=j*4+1;
        else if(v.z>0.5f)kv=j*4+2; else if(v.w>0.5f)kv=j*4+3;
    }
    g_ev[idx] = kv;
}

__global__ void k_G(const float* __restrict__ U_w,
                    const float* __restrict__ U_b,
                    const float* __restrict__ V_b){
    int idx = blockIdx.x*blockDim.x + threadIdx.x;
    if (idx >= Kn*ROWSn) return;
    int kv = idx / ROWSn;
    int r  = idx - kv*ROWSn;
    g_G[idx] = U_w[r*Kn + kv] + U_b[r] + V_b[r];
}

__device__ __forceinline__ void bg_barrier(int bg, unsigned want){
    __syncthreads();
    if (threadIdx.x == 0){
        __threadfence();
        unsigned t = atomicAdd(&g_barc[bg][0], 1u);
        if (t == ND_G-1){
            atomicExch(&g_barc[bg][0], 0u);
            __threadfence();
            atomicAdd(&g_barg[bg][0], 1u);
        } else {
            unsigned v;
            const unsigned* gp = &g_barg[bg][0];
            do { __nanosleep(32);
                 asm volatile("ld.global.cg.u32 %0,[%1];":"=r"(v):"l"(gp));
            } while (v < want);
            __threadfence();
        }
    }
    __syncthreads();
}

__global__ void __launch_bounds__(NT,1)
ctlstm_main(const void*  __restrict__ mask_raw,
            const float* __restrict__ times,
            const float* __restrict__ V_w,
            const float* __restrict__ Lw,
            const float* __restrict__ scale,
            float*       __restrict__ out)
{
    __shared__ float sm[SM_FLOATS];
    float* ht_s  = sm + HT_OFF;
    float* D_s   = sm + D_OFF;
    float* out_s = sm + OUT_OFF;
    float* hto_s = sm + HTO_OFF;
    float* lam_s = sm + LAM_OFF;
    float* m_s   = sm + M_OFF;       // [2][16]

    const int tid = threadIdx.x;
    const int cta = blockIdx.x;
    const int bg  = cta & (NB_G-1);
    const int dg  = cta >> 3;
    const int b0  = bg * 16;
    const int d0g = dg * 16;

    const int wrp = tid >> 5, lane = tid & 31;
    const int gid = lane >> 2, tig = lane & 3;

    const int pb  = tid >> 4, pd = tid & 15;     // pointwise cell (batch, dim)
    const int bgl = b0 + pb;
    const int dgl = d0g + pd;
    const int mm  = g_mask_mode;

    // ---- prologue: A fragments (weights) persistent in registers ----------
    uint32_t Af[128];
    {
        #pragma unroll
        for (int kt=0; kt<32; ++kt){
            int k = kt*8 + tig;
            float f0=0.f, f1=0.f, f2=0.f, f3=0.f;
            if (wrp < 7){
                const float* r0 = &V_w[(size_t)(wrp*256 + d0g + gid)*256];
                const float* r1 = r0 + 8*256;
                f0 = __ldg(r0+k);   f1 = __ldg(r1+k);
                f2 = __ldg(r0+k+4); f3 = __ldg(r1+k+4);
            } else if (gid < 4){
                const float* r0 = &Lw[(size_t)(dg*4 + gid)*256];
                f0 = __ldg(r0+k);   f2 = __ldg(r0+k+4);
            }
            Af[kt*4+0]=tf32r(f0); Af[kt*4+1]=tf32r(f1);
            Af[kt*4+2]=tf32r(f2); Af[kt*4+3]=tf32r(f3);
        }
    }
    float sc_l = 1.0f;
    if (wrp == 7 && gid < 4) sc_l = __ldg(&scale[dg*4 + gid]);

    for (int i = tid; i < 16*HT_ST; i += NT) ht_s[i] = 0.0f;
    if (tid < 32){ m_s[tid] = 0.0f; }
    __syncthreads();

    float ct = 0.0f, cb = 0.0f, htr = 0.0f;
    const size_t OFF1 = (size_t)Bn*En*Kn;
    const size_t BEH  = (size_t)Bn*En*HDn;

    for (int i = 0; i <= En; ++i){
        // ---- prefetch per-step scalars (scheduled under MMA) ---------------
        float bias[7]; float mval = 0.0f, dt = 0.0f;
        if (i < En){
            int kv = g_ev[bgl*En + i];
            #pragma unroll
            for (int g=0; g<7; ++g)
                bias[g] = __ldg(&g_G[(size_t)kv*ROWSn + g*256 + dgl]);
            int mi = bgl*En + i;
            if (mm==0)      mval = ((const unsigned char*)mask_raw)[mi] ? 1.0f:0.0f;
            else if (mm==1) mval = ((const int*)mask_raw)[mi] ? 1.0f:0.0f;
            else            mval = (((const float*)mask_raw)[mi]!=0.0f) ? 1.0f:0.0f;
            dt = __ldg(&times[bgl*(En+1)+i+1]) - __ldg(&times[bgl*(En+1)+i]);
        }

        // ---- GEMM: D[16 cols (this warp), 16 b] = W @ ht^T -----------------
        float dA[4] = {0,0,0,0}, dB[4] = {0,0,0,0};    // n-tile 0 (b0..7), 1 (b8..15)
        {
            const float* h0 = &ht_s[(0+gid)*HT_ST];
            const float* h1 = &ht_s[(8+gid)*HT_ST];
            #pragma unroll
            for (int kt=0; kt<32; ++kt){
                int k = kt*8 + tig;
                uint32_t bA0 = *(const uint32_t*)&h0[k];
                uint32_t bA1 = *(const uint32_t*)&h0[k+4];
                uint32_t bB0 = *(const uint32_t*)&h1[k];
                uint32_t bB1 = *(const uint32_t*)&h1[k+4];
                mma8(dA, &Af[kt*4], bA0, bA1);
                mma8(dB, &Af[kt*4], bB0, bB1);
            }
        }
        // store D frags: D_s[m(col 0..127)][b] stride 18
        {
            int m0 = wrp*16 + gid, m1 = m0 + 8;
            *(float2*)&D_s[m0*D_ST + 0 + 2*tig] = make_float2(dA[0], dA[1]);
            *(float2*)&D_s[m1*D_ST + 0 + 2*tig] = make_float2(dA[2], dA[3]);
            *(float2*)&D_s[m0*D_ST + 8 + 2*tig] = make_float2(dB[0], dB[1]);
            *(float2*)&D_s[m1*D_ST + 8 + 2*tig] = make_float2(dB[2], dB[3]);
        }
        __syncthreads();

        // ---- lambda staging for step i-1 (cols 112..115) -------------------
        if (i > 0 && wrp == 7 && gid < 4){
            const float* mp = &m_s[((i-1)&1)*16];
            #pragma unroll
            for (int nt=0; nt<2; ++nt){
                float v0 = (nt==0)? dA[0] : dB[0];
                float v1 = (nt==0)? dA[1] : dB[1];
                int bb = nt*8 + 2*tig;
                float x0 = __fdividef(v0, sc_l);
                float x1 = __fdividef(v1, sc_l);
                float l0 = sc_l * ((x0>20.0f)?x0:log1pf(__expf(x0)));
                float l1 = sc_l * ((x1>20.0f)?x1:log1pf(__expf(x1)));
                lam_s[bb*4 + gid]     = mp[bb]   * l0;
                lam_s[(bb+1)*4 + gid] = mp[bb+1] * l1;
            }
        }

        // ---- pointwise recurrence ------------------------------------------
        if (i < En){
            float nn[7];
            #pragma unroll
            for (int g=0; g<7; ++g)
                nn[g] = D_s[(g*16+pd)*D_ST + pb] + bias[g];
            float ig=sigf(nn[0]), fg=sigf(nn[1]), ib=sigf(nn[2]), fb=sigf(nn[3]);
            float z=2.0f*sigf(nn[4]), og=sigf(nn[5]);
            float x6=nn[6];
            float delta = (x6>20.0f)?x6:log1pf(__expf(x6));
            float clow = fg*ct + ig*z;
            float cbn  = fb*cb + ib*z;
            float ctn  = cbn + (clow-cbn)*__expf(-dt*delta);
            float htn  = og * tanhap(ctn);
            if (mval != 0.0f){ ct=ctn; cb=cbn; htr=htn; }

            int cell = pb*16 + pd;
            out_s[0*256+cell] = mval*clow;
            out_s[1*256+cell] = mval*cbn;
            out_s[2*256+cell] = mval*delta;
            out_s[3*256+cell] = mval*og;
            hto_s[cell] = __uint_as_float(tf32r(htr));   // tf32-rounded ht
            if (pd == 0) m_s[(i&1)*16 + pb] = mval;
        }
        __syncthreads();

        // ---- lambda store for step i-1 -------------------------------------
        if (i > 0 && tid < 16){
            float4 v = *(float4*)&lam_s[tid*4];
            *(float4*)&out[((size_t)(b0+tid)*En + (i-1))*Kn + dg*4] = v;
        }
        if (i == En) break;

        // ---- 4 main outputs: 64B-aligned float4 segments -------------------
        {
            int a  = tid >> 6;
            int rr = tid & 63;
            int bb = rr >> 2, d4 = rr & 3;
            float4 v = *(float4*)&out_s[a*256 + bb*16 + d4*4];
            float* dst = out + OFF1 + (size_t)a*BEH
                       + ((size_t)(b0+bb)*En + i)*HDn + d0g + d4*4;
            *(float4*)dst = v;
        }
        // ---- publish ht slice ----------------------------------------------
        float* hb = g_ht[i&1];
        if (tid < 64){
            int bb = tid >> 2, d4 = tid & 3;
            float4 v = *(float4*)&hto_s[bb*16 + d4*4];
            stcg4(&hb[(size_t)(b0+bb)*256 + d0g + d4*4], v);
        }

        bg_barrier(bg, (unsigned)(i+1));

        // ---- refill full ht (tf32 bits) for my 16 batches ------------------
        {
            uint32_t dbase = smem_u32(ht_s);
            #pragma unroll
            for (int j=0; j<4; ++j){
                int t  = tid + j*NT;
                int bb = t >> 6, kc = (t & 63)*4;
                cpa16(dbase + (uint32_t)(bb*HT_ST + kc)*4u,
                      &hb[(size_t)(b0+bb)*256 + kc]);
            }
            asm volatile("cp.async.commit_group;" ::: "memory");
            asm volatile("cp.async.wait_group 0;" ::: "memory");
        }
        __syncthreads();
    }
}

extern "C" void kernel_launch(void* const* d_in, const int* in_sizes, int n_in,
                              void* d_out, int out_size){
    const float* seq   = (const float*)d_in[0];
    const void*  mask  = d_in[1];
    const float* times = (const float*)d_in[2];
    const float* U_w   = (const float*)d_in[3];
    const float* U_b   = (const float*)d_in[4];
    const float* V_w   = (const float*)d_in[5];
    const float* V_b   = (const float*)d_in[6];
    const float* Lw    = (const float*)d_in[7];
    const float* scale = (const float*)d_in[8];
    float* out = (float*)d_out;

    k_init<<<1, 32>>>(mask);
    k_ev<<<(Bn*En + 127)/128, 128>>>(seq);
    k_G<<<(Kn*ROWSn + 255)/256, 256>>>(U_w, U_b, V_b);
    ctlstm_main<<<NCTA, NT>>>(mask, times, V_w, Lw, scale, out);
}

// round 16
// speedup vs baseline: 2.1311x; 1.2817x over previous
#include <cuda_runtime.h>
#include <cuda_bf16.h>
#include <cstdint>

#define Bn 128
#define En 1024
#define Kn 64
#define HDn 256
#define ROWSn 1792
#define NB_G 16
#define ND_G 16
#define NCTA 256
#define NT 256
#define BT 8

#define SHT 264        // ht_s row stride in bf16 units (528B: conflict-free B reads)
#define D_ST 18

__device__ int      g_ev[Bn*En];
__device__ float    g_G[Kn*ROWSn];
__device__ __align__(16) __nv_bfloat16 g_htb[2][Bn][HDn];
__device__ unsigned g_barc[NB_G][32];
__device__ unsigned g_barg[NB_G][32];
__device__ int      g_mask_mode;

__device__ __forceinline__ float sigf(float x){
    return __fdividef(1.0f, 1.0f + __expf(-x));
}
__device__ __forceinline__ float tanhap(float x){
    float y; asm("tanh.approx.f32 %0,%1;" : "=f"(y) : "f"(x)); return y;
}
__device__ __forceinline__ uint32_t pk(float x, float y){
    __nv_bfloat162 h = __floats2bfloat162_rn(x, y);
    return *(uint32_t*)&h;
}
__device__ __forceinline__ void mmab(float* d, const uint32_t* a,
                                     uint32_t b0, uint32_t b1){
    asm volatile("mma.sync.aligned.m16n8k16.row.col.f32.bf16.bf16.f32 "
        "{%0,%1,%2,%3},{%4,%5,%6,%7},{%8,%9},{%0,%1,%2,%3};"
        : "+f"(d[0]),"+f"(d[1]),"+f"(d[2]),"+f"(d[3])
        : "r"(a[0]),"r"(a[1]),"r"(a[2]),"r"(a[3]),"r"(b0),"r"(b1));
}
__device__ __forceinline__ uint32_t smem_u32(const void* p){
    uint32_t a;
    asm("{ .reg .u64 t; cvta.to.shared.u64 t,%1; cvt.u32.u64 %0,t; }":"=r"(a):"l"(p));
    return a;
}
__device__ __forceinline__ void cpa16(uint32_t dst, const void* src){
    asm volatile("cp.async.cg.shared.global [%0],[%1],16;" :: "r"(dst),"l"(src));
}
__device__ __forceinline__ void stcg4u(void* p, uint4 v){
    asm volatile("st.global.cg.v4.b32 [%0],{%1,%2,%3,%4};"
                 :: "l"(p),"r"(v.x),"r"(v.y),"r"(v.z),"r"(v.w) : "memory");
}

__global__ void k_init(const void* mask){
    if (threadIdx.x < NB_G){
        g_barc[threadIdx.x][0] = 0u;
        g_barg[threadIdx.x][0] = 0u;
    }
    if (threadIdx.x == 0){
        const float* mf = (const float*)mask;
        const int*   mi = (const int*)mask;
        bool okf=true, oki=true, anyf=false, anyi=false;
        for (int j=0;j<256;++j){
            float fv=mf[j];
            if(!(fv==0.0f||fv==1.0f)) okf=false; else if(fv==1.0f) anyf=true;
            int iv=mi[j];
            if(!(iv==0||iv==1)) oki=false; else if(iv==1) anyi=true;
        }
        g_mask_mode = (okf&&anyf)?2:((oki&&anyi)?1:0);
    }
}

__global__ void k_ev(const float* __restrict__ seq){
    int idx = blockIdx.x*blockDim.x + threadIdx.x;
    if (idx >= Bn*En) return;
    const float4* p = (const float4*)&seq[(size_t)idx*Kn];
    int kv = 0;
    #pragma unroll
    for (int j=0;j<Kn/4;++j){
        float4 v = __ldg(&p[j]);
        if(v.x>0.5f)kv=j*4; else if(v.y>0.5f)kv=j*4+1;
        else if(v.z>0.5f)kv=j*4+2; else if(v.w>0.5f)kv=j*4+3;
    }
    g_ev[idx] = kv;
}

__global__ void k_G(const float* __restrict__ U_w,
                    const float* __restrict__ U_b,
                    const float* __restrict__ V_b){
    int idx = blockIdx.x*blockDim.x + threadIdx.x;
    if (idx >= Kn*ROWSn) return;
    int kv = idx / ROWSn;
    int r  = idx - kv*ROWSn;
    g_G[idx] = U_w[r*Kn + kv] + U_b[r] + V_b[r];
}

__device__ __forceinline__ void bg_barrier(int bg, unsigned want){
    __syncthreads();
    if (threadIdx.x == 0){
        __threadfence();
        unsigned t = atomicAdd(&g_barc[bg][0], 1u);
        if (t == ND_G-1){
            atomicExch(&g_barc[bg][0], 0u);
            __threadfence();
            atomicAdd(&g_barg[bg][0], 1u);
        } else {
            unsigned v;
            const unsigned* gp = &g_barg[bg][0];
            do { __nanosleep(16);
                 asm volatile("ld.global.cg.u32 %0,[%1];":"=r"(v):"l"(gp));
            } while (v < want);
            __threadfence();
        }
    }
    __syncthreads();
}

__global__ void __launch_bounds__(NT,2)
ctlstm_main(const void*  __restrict__ mask_raw,
            const float* __restrict__ times,
            const float* __restrict__ V_w,
            const float* __restrict__ Lw,
            const float* __restrict__ scale,
            float*       __restrict__ out)
{
    __shared__ __nv_bfloat16 ht_s[BT*SHT];           // 4224 B
    __shared__ float D_s[128*D_ST];                  // 9216 B
    __shared__ float out_s[4*BT*16];                 // 2048 B
    __shared__ __nv_bfloat16 hto_s[BT*16];           // 256 B
    __shared__ float lam_s[BT*4];
    __shared__ float m_s[2][BT];

    const int tid = threadIdx.x;
    const int cta = blockIdx.x;
    const int bg  = cta & (NB_G-1);
    const int dg  = cta >> 4;
    const int b0  = bg * BT;
    const int d0g = dg * 16;

    const int wrp = tid >> 5, lane = tid & 31;
    const int gid = lane >> 2, tig = lane & 3;

    const int pb  = (tid >> 4) & 7, pd = tid & 15;   // pointwise cell (tid<128)
    const int bgl = b0 + pb;
    const int dgl = d0g + pd;
    const int mm  = g_mask_mode;

    // ---- prologue: bf16 A fragments (weights) persistent in registers -----
    uint32_t Af[64];
    #pragma unroll
    for (int kt=0; kt<16; ++kt){
        int k = kt*16 + tig*2;
        float w00=0.f,w01=0.f,w10=0.f,w11=0.f;   // rows gid / gid+8, k / k+1
        float w02=0.f,w03=0.f,w12=0.f,w13=0.f;   // k+8 / k+9
        if (wrp < 7){
            const float* r0 = &V_w[(size_t)(wrp*256 + d0g + gid)*256];
            const float* r1 = r0 + 8*256;
            w00=__ldg(r0+k);   w01=__ldg(r0+k+1);
            w10=__ldg(r1+k);   w11=__ldg(r1+k+1);
            w02=__ldg(r0+k+8); w03=__ldg(r0+k+9);
            w12=__ldg(r1+k+8); w13=__ldg(r1+k+9);
        } else if (gid < 4){
            const float* r0 = &Lw[(size_t)(dg*4 + gid)*256];
            w00=__ldg(r0+k);   w01=__ldg(r0+k+1);
            w02=__ldg(r0+k+8); w03=__ldg(r0+k+9);
        }
        Af[kt*4+0]=pk(w00,w01); Af[kt*4+1]=pk(w10,w11);
        Af[kt*4+2]=pk(w02,w03); Af[kt*4+3]=pk(w12,w13);
    }
    float sc_l = 1.0f;
    if (wrp == 7 && gid < 4) sc_l = __ldg(&scale[dg*4 + gid]);

    for (int i = tid; i < BT*SHT/2; i += NT) ((uint32_t*)ht_s)[i] = 0u;
    if (tid < 16) m_s[tid>>3][tid&7] = 0.0f;
    __syncthreads();

    float ct = 0.0f, cb = 0.0f, htr = 0.0f;
    const size_t OFF1 = (size_t)Bn*En*Kn;
    const size_t BEH  = (size_t)Bn*En*HDn;

    for (int i = 0; i <= En; ++i){
        // ---- prefetch per-step scalars -------------------------------------
        float bias[7]; float mval = 0.0f, dt = 0.0f;
        if (i < En && tid < 128){
            int kv = g_ev[bgl*En + i];
            #pragma unroll
            for (int g=0; g<7; ++g)
                bias[g] = __ldg(&g_G[(size_t)kv*ROWSn + g*256 + dgl]);
            int mi = bgl*En + i;
            if (mm==0)      mval = ((const unsigned char*)mask_raw)[mi] ? 1.0f:0.0f;
            else if (mm==1) mval = ((const int*)mask_raw)[mi] ? 1.0f:0.0f;
            else            mval = (((const float*)mask_raw)[mi]!=0.0f) ? 1.0f:0.0f;
            dt = __ldg(&times[bgl*(En+1)+i+1]) - __ldg(&times[bgl*(En+1)+i]);
        }

        // ---- GEMM: D[16 cols (this warp), 8 b] = W @ ht^T ------------------
        float dA[4] = {0,0,0,0}, dB[4] = {0,0,0,0};
        {
            const char* hrow = (const char*)ht_s + gid*(SHT*2) + tig*4;
            #pragma unroll
            for (int kt=0; kt<16; ++kt){
                uint32_t b0r = *(const uint32_t*)(hrow + kt*32);
                uint32_t b1r = *(const uint32_t*)(hrow + kt*32 + 16);
                mmab((kt&1) ? dB : dA, &Af[kt*4], b0r, b1r);
            }
            #pragma unroll
            for (int j=0;j<4;++j) dA[j] += dB[j];
        }
        {
            int m0 = wrp*16 + gid, m1 = m0 + 8;
            *(float2*)&D_s[m0*D_ST + 2*tig] = make_float2(dA[0], dA[1]);
            *(float2*)&D_s[m1*D_ST + 2*tig] = make_float2(dA[2], dA[3]);
        }
        __syncthreads();

        // ---- lambda staging for step i-1 (cols 112..115, warp 7) -----------
        if (i > 0 && wrp == 7 && gid < 4){
            const float* mp = m_s[(i-1)&1];
            int bb = 2*tig;
            float x0 = __fdividef(dA[0], sc_l);
            float x1 = __fdividef(dA[1], sc_l);
            float l0 = sc_l * ((x0>20.0f)?x0:log1pf(__expf(x0)));
            float l1 = sc_l * ((x1>20.0f)?x1:log1pf(__expf(x1)));
            lam_s[bb*4 + gid]     = mp[bb]   * l0;
            lam_s[(bb+1)*4 + gid] = mp[bb+1] * l1;
        }

        // ---- pointwise recurrence (threads 0-127) --------------------------
        if (i < En && tid < 128){
            float nn[7];
            #pragma unroll
            for (int g=0; g<7; ++g)
                nn[g] = D_s[(g*16+pd)*D_ST + pb] + bias[g];
            float ig=sigf(nn[0]), fg=sigf(nn[1]), ib=sigf(nn[2]), fb=sigf(nn[3]);
            float z=2.0f*sigf(nn[4]), og=sigf(nn[5]);
            float x6=nn[6];
            float delta = (x6>20.0f)?x6:log1pf(__expf(x6));
            float clow = fg*ct + ig*z;
            float cbn  = fb*cb + ib*z;
            float ctn  = cbn + (clow-cbn)*__expf(-dt*delta);
            float htn  = og * tanhap(ctn);
            if (mval != 0.0f){ ct=ctn; cb=cbn; htr=htn; }

            int cell = pb*16 + pd;
            out_s[0*128+cell] = mval*clow;
            out_s[1*128+cell] = mval*cbn;
            out_s[2*128+cell] = mval*delta;
            out_s[3*128+cell] = mval*og;
            hto_s[cell] = __float2bfloat16_rn(htr);
            if (pd == 0) m_s[i&1][pb] = mval;
        }
        __syncthreads();

        // ---- lambda store for step i-1 -------------------------------------
        if (i > 0 && tid < BT){
            float4 v = *(float4*)&lam_s[tid*4];
            *(float4*)&out[((size_t)(b0+tid)*En + (i-1))*Kn + dg*4] = v;
        }
        if (i == En) break;

        // ---- 4 main outputs: 64B-aligned float4 segments -------------------
        if (tid < 128){
            int a  = tid >> 5;
            int rr = tid & 31;
            int bb = rr >> 2, d4 = rr & 3;
            float4 v = *(float4*)&out_s[a*128 + bb*16 + d4*4];
            float* dst = out + OFF1 + (size_t)a*BEH
                       + ((size_t)(b0+bb)*En + i)*HDn + d0g + d4*4;
            *(float4*)dst = v;
        }
        // ---- publish bf16 ht slice (16B per half-row) ----------------------
        if (tid < 16){
            int bb = tid >> 1, h = tid & 1;
            uint4 v = *(uint4*)((const char*)hto_s + bb*32 + h*16);
            stcg4u(&g_htb[i&1][b0+bb][d0g + h*8], v);
        }

        bg_barrier(bg, (unsigned)(i+1));

        // ---- refill bf16 ht (8 b x 256 k) via cp.async ---------------------
        {
            uint32_t dbase = smem_u32(ht_s);
            int bb = tid >> 5, cc = tid & 31;
            cpa16(dbase + (uint32_t)(bb*(SHT*2) + cc*16),
                  &g_htb[i&1][b0+bb][cc*8]);
            asm volatile("cp.async.commit_group;" ::: "memory");
            asm volatile("cp.async.wait_group 0;" ::: "memory");
        }
        __syncthreads();
    }
}

extern "C" void kernel_launch(void* const* d_in, const int* in_sizes, int n_in,
                              void* d_out, int out_size){
    const float* seq   = (const float*)d_in[0];
    const void*  mask  = d_in[1];
    const float* times = (const float*)d_in[2];
    const float* U_w   = (const float*)d_in[3];
    const float* U_b   = (const float*)d_in[4];
    const float* V_w   = (const float*)d_in[5];
    const float* V_b   = (const float*)d_in[6];
    const float* Lw    = (const float*)d_in[7];
    const float* scale = (const float*)d_in[8];
    float* out = (float*)d_out;

    k_init<<<1, 32>>>(mask);
    k_ev<<<(Bn*En + 127)/128, 128>>>(seq);
    k_G<<<(Kn*ROWSn + 255)/256, 256>>>(U_w, U_b, V_b);
    ctlstm_main<<<NCTA, NT>>>(mask, times, V_w, Lw, scale, out);
}